// round 1
// baseline (speedup 1.0000x reference)
#include <cuda_runtime.h>
#include <cuda_bf16.h>

// ---------------- constants ----------------
#define D_MODEL 1024
#define FFN     4096
#define TWOFFN  8192
#define TSEQ    4096
#define BATCH   2
#define CHUNK   256
#define NC      16
#define TTT_LR  0.01f
#define KSIZE   5

#define BM 128
#define BN 128
#define BK 8

typedef unsigned long long u64;

// ---------------- device scratch (no allocations allowed) ----------------
__device__ float g_gu[(size_t)8192 * 8192];          // gate_up   268MB
__device__ float g_h [(size_t)8192 * 4096];          // h         134MB
__device__ float g_t [(size_t)BATCH * TSEQ * D_MODEL];   // conv out
__device__ float g_tp[(size_t)BATCH * 3840 * D_MODEL];   // t_proj (chunks 0..14)
__device__ float g_dd[(size_t)BATCH * 15 * D_MODEL * FFN]; // d_down -> cumsum in place, 503MB

// ---------------- packed f32x2 helpers ----------------
__device__ __forceinline__ u64 splat2(float a) {
    u64 r; asm("mov.b64 %0, {%1, %1};" : "=l"(r) : "f"(a)); return r;
}
__device__ __forceinline__ void fma2(u64& c, u64 a, u64 b) {
    asm("fma.rn.f32x2 %0, %1, %2, %0;" : "+l"(c) : "l"(a), "l"(b));
}
union U64F2 { u64 u; float2 f; };

// ---------------- tiled GEMM body ----------------
// MODE 0: NT  (A[m*lda+k], B[n*ldb+k])
// MODE 1: TN  (A[k*lda+m], B[k*ldb+n])
// MODE 2: NT with composed B: Beff = B + scale2 * B2
// C[m,n], 128x128 tile, 256 threads, 8x8 per thread, K multiple of 8.
template <int MODE>
__device__ __forceinline__ void gemm_body(
    const float* __restrict__ A, const float* __restrict__ B,
    const float* __restrict__ B2, float scale2,
    int K, int lda, int ldb, float* __restrict__ C, int ldc)
{
    __shared__ __align__(16) float As[BK][BM];
    __shared__ __align__(16) float Bs[BK][BN];

    const int tid = threadIdx.x;
    const int tx = tid & 15;      // col group
    const int ty = tid >> 4;      // row group

    u64 acc[8][4];
#pragma unroll
    for (int i = 0; i < 8; i++)
#pragma unroll
        for (int j = 0; j < 4; j++) acc[i][j] = 0ULL;

    // NT load mapping: one float4 per thread per operand
    const int lrow = tid >> 1;          // 0..127 (m or n)
    const int lseg = (tid & 1) * 4;     // k offset 0/4
    // TN load mapping
    const int tkrow = tid >> 5;         // 0..7 (k)
    const int tmseg = (tid & 31) * 4;   // 0..124 (m or n)

    for (int kt = 0; kt < K; kt += BK) {
        if (MODE == 1) {
            float4 a = *(const float4*)(A + (kt + tkrow) * lda + tmseg);
            float4 b = *(const float4*)(B + (kt + tkrow) * ldb + tmseg);
            *(float4*)&As[tkrow][tmseg] = a;
            *(float4*)&Bs[tkrow][tmseg] = b;
        } else {
            float4 a = *(const float4*)(A + lrow * lda + kt + lseg);
            float4 b = *(const float4*)(B + lrow * ldb + kt + lseg);
            if (MODE == 2) {
                float4 b2 = *(const float4*)(B2 + lrow * ldb + kt + lseg);
                b.x += scale2 * b2.x; b.y += scale2 * b2.y;
                b.z += scale2 * b2.z; b.w += scale2 * b2.w;
            }
            As[lseg + 0][lrow] = a.x; As[lseg + 1][lrow] = a.y;
            As[lseg + 2][lrow] = a.z; As[lseg + 3][lrow] = a.w;
            Bs[lseg + 0][lrow] = b.x; Bs[lseg + 1][lrow] = b.y;
            Bs[lseg + 2][lrow] = b.z; Bs[lseg + 3][lrow] = b.w;
        }
        __syncthreads();
#pragma unroll
        for (int k = 0; k < BK; k++) {
            float4 a0 = *(const float4*)&As[k][ty * 8];
            float4 a1 = *(const float4*)&As[k][ty * 8 + 4];
            ulonglong2 b01 = *(const ulonglong2*)&Bs[k][tx * 8];
            ulonglong2 b23 = *(const ulonglong2*)&Bs[k][tx * 8 + 4];
            float av[8] = {a0.x, a0.y, a0.z, a0.w, a1.x, a1.y, a1.z, a1.w};
#pragma unroll
            for (int i = 0; i < 8; i++) {
                u64 ai = splat2(av[i]);
                fma2(acc[i][0], ai, b01.x);
                fma2(acc[i][1], ai, b01.y);
                fma2(acc[i][2], ai, b23.x);
                fma2(acc[i][3], ai, b23.y);
            }
        }
        __syncthreads();
    }

#pragma unroll
    for (int i = 0; i < 8; i++) {
        U64F2 v0, v1, v2, v3;
        v0.u = acc[i][0]; v1.u = acc[i][1]; v2.u = acc[i][2]; v3.u = acc[i][3];
        float* crow = C + (size_t)(ty * 8 + i) * ldc + tx * 8;
        *(float4*)crow       = make_float4(v0.f.x, v0.f.y, v1.f.x, v1.f.y);
        *(float4*)(crow + 4) = make_float4(v2.f.x, v2.f.y, v3.f.x, v3.f.y);
    }
}

// ---------------- GEMM wrapper kernels ----------------
// Generic NT with z-batching: used for G1 (gate_up) and G2 (t_proj)
__global__ void k_gemm_nt(const float* __restrict__ A, const float* __restrict__ B,
                          float* __restrict__ C, int K, int lda, int ldb, int ldc,
                          long long sA, long long sB, long long sC)
{
    const float* Ab = A + (long long)blockIdx.z * sA + (long long)blockIdx.y * BM * lda;
    const float* Bb = B + (long long)blockIdx.z * sB + (long long)blockIdx.x * BN * ldb;
    float* Cb = C + (long long)blockIdx.z * sC + (long long)blockIdx.y * BM * ldc
                  + (long long)blockIdx.x * BN;
    gemm_body<0>(Ab, Bb, nullptr, 0.f, K, lda, ldb, Cb, ldc);
}

// G3: d_down[b,j,d,h] = sum_c tp[b,j*256+c, d] * h[b,j*256+c, h]   (TN)
__global__ void k_gemm3(const float* __restrict__ tp, const float* __restrict__ h,
                        float* __restrict__ dd)
{
    int z = blockIdx.z;           // 0..29
    int b = z / 15, j = z % 15;
    const float* Ab = tp + ((long long)(b * 3840 + j * CHUNK)) * D_MODEL
                         + (long long)blockIdx.y * BM;
    const float* Bb = h + ((long long)(b * TSEQ + j * CHUNK)) * FFN
                        + (long long)blockIdx.x * BN;
    float* Cb = dd + (long long)z * D_MODEL * FFN
                   + (long long)blockIdx.y * BM * FFN + (long long)blockIdx.x * BN;
    gemm_body<1>(Ab, Bb, nullptr, 0.f, CHUNK, D_MODEL, FFN, Cb, FFN);
}

// G4: out[b, j*256+c, d] = sum_h h[b,j*256+c,h] * (w_down + LR*ddcum[b,j-1])[d,h]
__global__ void k_gemm4(const float* __restrict__ h, const float* __restrict__ wdown,
                        const float* __restrict__ ddc, float* __restrict__ out)
{
    int z = blockIdx.z;           // 0..31
    int b = z >> 4, j = z & 15;
    const float* Ab = h + ((long long)(b * TSEQ + j * CHUNK)) * FFN
                        + (long long)blockIdx.y * BM * FFN;
    const float* Bw = wdown + (long long)blockIdx.x * BN * FFN;
    float* Cb = out + ((long long)(b * TSEQ + j * CHUNK)) * D_MODEL
                    + (long long)blockIdx.y * BM * D_MODEL + (long long)blockIdx.x * BN;
    if (j == 0) {
        gemm_body<0>(Ab, Bw, nullptr, 0.f, FFN, FFN, FFN, Cb, D_MODEL);
    } else {
        const float* Bd = ddc + ((long long)(b * 15 + (j - 1))) * D_MODEL * FFN
                              + (long long)blockIdx.x * BN * FFN;
        gemm_body<2>(Ab, Bw, Bd, TTT_LR, FFN, FFN, FFN, Cb, D_MODEL);
    }
}

// ---------------- elementwise kernels ----------------
__global__ void k_conv(const float* __restrict__ tt, const float* __restrict__ cw,
                       const float* __restrict__ cb, float* __restrict__ t)
{
    long long idx = (long long)blockIdx.x * blockDim.x + threadIdx.x;
    if (idx >= (long long)BATCH * TSEQ * D_MODEL) return;
    int d = (int)(idx % D_MODEL);
    long long bi = idx / D_MODEL;
    int i = (int)(bi % TSEQ);
    int b = (int)(bi / TSEQ);
    const float* base = tt + (long long)b * TSEQ * D_MODEL + d;
    float acc = cb[d];
#pragma unroll
    for (int k = 0; k < KSIZE; k++) {
        int src = i - (KSIZE - 1) + k;
        if (src >= 0) acc += base[(long long)src * D_MODEL] * cw[d * KSIZE + k];
    }
    t[idx] = acc;
}

__global__ void k_swiglu(const float* __restrict__ gu, float* __restrict__ h)
{
    long long idx = (long long)blockIdx.x * blockDim.x + threadIdx.x;
    if (idx >= (long long)8192 * FFN) return;
    long long m = idx >> 12;          // FFN = 4096
    int f = (int)(idx & (FFN - 1));
    float g = gu[m * TWOFFN + f];
    float u = gu[m * TWOFFN + FFN + f];
    float s = g / (1.0f + expf(-g));
    h[idx] = s * u;
}

// in-place cumsum of d_down over the 15 chunks (per batch, per (d,h))
__global__ void k_cumsum(float* __restrict__ dd)
{
    long long idx = (long long)blockIdx.x * blockDim.x + threadIdx.x;
    const long long DF = (long long)D_MODEL * FFN;   // 4194304
    if (idx >= (long long)BATCH * DF) return;
    int b = idx >= DF;
    long long off = idx - (long long)b * DF;
    float* base = dd + (long long)b * 15 * DF + off;
    float acc = 0.f;
#pragma unroll
    for (int j = 0; j < 15; j++) {
        acc += base[(long long)j * DF];
        base[(long long)j * DF] = acc;
    }
}

// ---------------- launch ----------------
extern "C" void kernel_launch(void* const* d_in, const int* in_sizes, int n_in,
                              void* d_out, int out_size)
{
    const float* x     = (const float*)d_in[0];
    const float* tt    = (const float*)d_in[1];
    const float* wgu   = (const float*)d_in[2];
    const float* wdown = (const float*)d_in[3];
    const float* proj  = (const float*)d_in[4];
    const float* cw    = (const float*)d_in[5];
    const float* cb    = (const float*)d_in[6];
    float* out = (float*)d_out;

    float *gu, *h, *t, *tp, *dd;
    cudaGetSymbolAddress((void**)&gu, g_gu);
    cudaGetSymbolAddress((void**)&h,  g_h);
    cudaGetSymbolAddress((void**)&t,  g_t);
    cudaGetSymbolAddress((void**)&tp, g_tp);
    cudaGetSymbolAddress((void**)&dd, g_dd);

    // 1) causal depthwise conv on ttt_target
    k_conv<<<(BATCH * TSEQ * D_MODEL + 255) / 256, 256>>>(tt, cw, cb, t);

    // 2) G1: gate_up = x @ w_gate_up^T   (M=8192, N=8192, K=1024)
    k_gemm_nt<<<dim3(TWOFFN / BN, 8192 / BM, 1), 256>>>(
        x, wgu, gu, D_MODEL, D_MODEL, D_MODEL, TWOFFN, 0, 0, 0);

    // 3) SwiGLU: h = silu(gate) * up
    k_swiglu<<<(int)(((long long)8192 * FFN + 255) / 256), 256>>>(gu, h);

    // 4) G2: tp = t @ ttt_proj^T for chunks 0..14  (M=3840/batch, N=1024, K=1024)
    k_gemm_nt<<<dim3(D_MODEL / BN, 3840 / BM, BATCH), 256>>>(
        t, proj, tp, D_MODEL, D_MODEL, D_MODEL, D_MODEL,
        (long long)TSEQ * D_MODEL, 0, (long long)3840 * D_MODEL);

    // 5) G3: d_down per (b, j<15)  (M=1024, N=4096, K=256)
    k_gemm3<<<dim3(FFN / BN, D_MODEL / BM, BATCH * 15), 256>>>(tp, h, dd);

    // 6) in-place chunk cumsum of d_down
    k_cumsum<<<(int)(((long long)BATCH * D_MODEL * FFN + 255) / 256), 256>>>(dd);

    // 7) G4: out = h_chunk @ (w_down + LR*ddcum)^T  (M=256, N=1024, K=4096) x 32
    k_gemm4<<<dim3(D_MODEL / BN, CHUNK / BM, BATCH * NC), 256>>>(h, wdown, dd, out);
}

// round 3
// speedup vs baseline: 2.0045x; 2.0045x over previous
#include <cuda_runtime.h>
#include <cuda_bf16.h>
#include <cstdint>

// ================= constants =================
#define D_MODEL 1024
#define FFN     4096
#define TSEQ    4096
#define BATCH   2
#define CHUNK   256
#define TTT_LR  0.01f
#define KSIZE   5

#define BM 128
#define BN 128
#define BK 32
#define STAGES 3
#define APITCH 80                       // bytes per row (32 bf16 + 8 pad)
#define ASZ (128 * APITCH)              // 10240 B per stage per operand
#define SMEM_BYTES (STAGES * 2 * ASZ)   // 61440

typedef unsigned long long u64;
typedef __nv_bfloat16 bf16;

// ================= device scratch =================
__device__ __align__(16) float g_gu [(size_t)8192 * 8192];            // 268MB
__device__ __align__(16) bf16  g_h_hi[(size_t)8192 * 4096];
__device__ __align__(16) bf16  g_h_lo[(size_t)8192 * 4096];
__device__ __align__(16) bf16  g_hT_hi[(size_t)8192 * 4096];
__device__ __align__(16) bf16  g_hT_lo[(size_t)8192 * 4096];
__device__ __align__(16) bf16  g_x_hi[(size_t)8192 * 1024];
__device__ __align__(16) bf16  g_x_lo[(size_t)8192 * 1024];
__device__ __align__(16) bf16  g_wgu_hi[(size_t)8192 * 1024];
__device__ __align__(16) bf16  g_wgu_lo[(size_t)8192 * 1024];
__device__ __align__(16) bf16  g_proj_hi[(size_t)1024 * 1024];
__device__ __align__(16) bf16  g_proj_lo[(size_t)1024 * 1024];
__device__ __align__(16) bf16  g_t_hi[(size_t)BATCH * 4096 * 1024];
__device__ __align__(16) bf16  g_t_lo[(size_t)BATCH * 4096 * 1024];
__device__ __align__(16) float g_tp  [(size_t)BATCH * 3840 * 1024];
__device__ __align__(16) bf16  g_tpT_hi[(size_t)BATCH * 1024 * 3840];
__device__ __align__(16) bf16  g_tpT_lo[(size_t)BATCH * 1024 * 3840];
__device__ __align__(16) float g_dd [(size_t)BATCH * 15 * 1024 * 4096];   // 503MB
__device__ __align__(16) bf16  g_wa_hi[(size_t)BATCH * 16 * 1024 * 4096]; // 268MB
__device__ __align__(16) bf16  g_wa_lo[(size_t)BATCH * 16 * 1024 * 4096]; // 268MB

// ================= PTX helpers (family-portable only) =================
__device__ __forceinline__ uint32_t smem_u32(const void* p) {
    uint32_t a;
    asm("{ .reg .u64 t; cvta.to.shared.u64 t, %1; cvt.u32.u64 %0, t; }" : "=r"(a) : "l"(p));
    return a;
}
__device__ __forceinline__ void cp_async16(uint32_t sdst, const void* gsrc) {
    asm volatile("cp.async.cg.shared.global [%0], [%1], 16;" :: "r"(sdst), "l"(gsrc) : "memory");
}
__device__ __forceinline__ void cp_commit() {
    asm volatile("cp.async.commit_group;" ::: "memory");
}
__device__ __forceinline__ void ldm_x4(uint32_t addr, uint32_t& r0, uint32_t& r1,
                                       uint32_t& r2, uint32_t& r3) {
    asm volatile("ldmatrix.sync.aligned.m8n8.x4.shared.b16 {%0,%1,%2,%3}, [%4];"
                 : "=r"(r0), "=r"(r1), "=r"(r2), "=r"(r3) : "r"(addr));
}
__device__ __forceinline__ void mma16816(float* c, const uint32_t* a, uint32_t b0, uint32_t b1) {
    asm volatile("mma.sync.aligned.m16n8k16.row.col.f32.bf16.bf16.f32 "
                 "{%0,%1,%2,%3}, {%4,%5,%6,%7}, {%8,%9}, {%0,%1,%2,%3};"
                 : "+f"(c[0]), "+f"(c[1]), "+f"(c[2]), "+f"(c[3])
                 : "r"(a[0]), "r"(a[1]), "r"(a[2]), "r"(a[3]), "r"(b0), "r"(b1));
}

// ================= HMMA GEMM: C[m,n] = sum_k A[m,k]*B[n,k], bf16 hi/lo split =================
// 3 K-passes: (Ahi,Bhi), (Ahi,Blo), (Alo,Bhi).  fp32 output.
__global__ __launch_bounds__(256, 2) void k_mma(
    const bf16* __restrict__ Ahi, const bf16* __restrict__ Alo, long long lda,
    const bf16* __restrict__ Bhi, const bf16* __restrict__ Blo, long long ldb,
    float* __restrict__ C, long long ldc, int K, int Z2,
    long long sA1, long long sA2, long long sB1, long long sB2,
    long long sC1, long long sC2)
{
    extern __shared__ char smem[];
    const uint32_t sb = smem_u32(smem);
    const int tid = threadIdx.x;
    const int lane = tid & 31;
    const int warp = tid >> 5;
    const int wm = warp >> 2;     // 0..1
    const int wn = warp & 3;      // 0..3

    const int z = blockIdx.z, z1 = Z2 > 1 ? z / Z2 : z, z2 = Z2 > 1 ? z % Z2 : 0;
    const long long aoff = (long long)z1 * sA1 + (long long)z2 * sA2 + (long long)blockIdx.y * BM * lda;
    const long long boff = (long long)z1 * sB1 + (long long)z2 * sB2 + (long long)blockIdx.x * BN * ldb;
    Ahi += aoff; Alo += aoff;
    Bhi += boff; Blo += boff;
    C   += (long long)z1 * sC1 + (long long)z2 * sC2
         + (long long)blockIdx.y * BM * ldc + (long long)blockIdx.x * BN;

    const int KI = K / BK;
    const int total = 3 * KI;

    float acc[4][4][4];
#pragma unroll
    for (int i = 0; i < 4; i++)
#pragma unroll
        for (int n = 0; n < 4; n++)
#pragma unroll
            for (int r = 0; r < 4; r++) acc[i][n][r] = 0.f;

    // per-thread load mapping: chunks c = tid, tid+256 per operand
    const int lrow0 = tid >> 2;          // rows tid/4 and tid/4+64
    const int lko   = (tid & 3);         // 16B chunk in row

    auto issue_load = [&](int it) {
        const int seg = (it >= 2 * KI) ? 2 : (it >= KI ? 1 : 0);
        const bf16* Ag = (seg == 2) ? Alo : Ahi;
        const bf16* Bg = (seg == 1) ? Blo : Bhi;
        const int kk = (it - seg * KI) * BK;
        const int s = it % STAGES;
        const uint32_t sa = sb + s * ASZ;
        const uint32_t sB = sb + (STAGES + s) * ASZ;
#pragma unroll
        for (int q = 0; q < 2; q++) {
            const int row = lrow0 + q * 64;
            const uint32_t so = (uint32_t)row * APITCH + lko * 16;
            cp_async16(sa + so, Ag + (size_t)row * lda + kk + lko * 8);
            cp_async16(sB + so, Bg + (size_t)row * ldb + kk + lko * 8);
        }
    };

#pragma unroll
    for (int s = 0; s < STAGES - 1; s++) {
        if (s < total) issue_load(s);
        cp_commit();
    }

    // ldmatrix per-thread base offsets
    const uint32_t aRow = (uint32_t)(wm * 64 + (lane & 15));
    const uint32_t bRow = (uint32_t)(wn * 32 + (lane & 15));
    const uint32_t kByte = (uint32_t)((lane >> 4) * 16);

    for (int it = 0; it < total; ++it) {
        asm volatile("cp.async.wait_group %0;" :: "n"(STAGES - 2) : "memory");
        __syncthreads();
        const int nx = it + STAGES - 1;
        if (nx < total) issue_load(nx);
        cp_commit();

        const int s = it % STAGES;
        const uint32_t sa = sb + s * ASZ;
        const uint32_t sB = sb + (STAGES + s) * ASZ;
#pragma unroll
        for (int k16 = 0; k16 < 2; k16++) {
            uint32_t a[4][4], b[2][4];
#pragma unroll
            for (int i = 0; i < 4; i++)
                ldm_x4(sa + (aRow + i * 16) * APITCH + kByte + k16 * 32,
                       a[i][0], a[i][1], a[i][2], a[i][3]);
#pragma unroll
            for (int j = 0; j < 2; j++)
                ldm_x4(sB + (bRow + j * 16) * APITCH + kByte + k16 * 32,
                       b[j][0], b[j][1], b[j][2], b[j][3]);
#pragma unroll
            for (int i = 0; i < 4; i++) {
#pragma unroll
                for (int n = 0; n < 4; n++) {
                    const int j = n >> 1, h = n & 1;
                    mma16816(acc[i][n], a[i], b[j][h], b[j][h + 2]);
                }
            }
        }
    }

    // epilogue
    const int g = lane >> 2, t2 = (lane & 3) * 2;
#pragma unroll
    for (int i = 0; i < 4; i++) {
        const int r = wm * 64 + i * 16 + g;
#pragma unroll
        for (int n = 0; n < 4; n++) {
            const int cc = wn * 32 + (n >> 1) * 16 + (n & 1) * 8 + t2;
            *(float2*)&C[(size_t)r * ldc + cc]       = make_float2(acc[i][n][0], acc[i][n][1]);
            *(float2*)&C[(size_t)(r + 8) * ldc + cc] = make_float2(acc[i][n][2], acc[i][n][3]);
        }
    }
}

// ================= elementwise kernels =================
__device__ __forceinline__ void split_bf16(float v, bf16& hi, bf16& lo) {
    hi = __float2bfloat16(v);
    lo = __float2bfloat16(v - __bfloat162float(hi));
}

__global__ void k_convert(const float* __restrict__ in, bf16* __restrict__ hi,
                          bf16* __restrict__ lo, long long n)
{
    long long i = (long long)blockIdx.x * blockDim.x + threadIdx.x;
    if (i >= n) return;
    bf16 h, l; split_bf16(in[i], h, l);
    hi[i] = h; lo[i] = l;
}

__global__ void k_conv_split(const float* __restrict__ tt, const float* __restrict__ cw,
                             const float* __restrict__ cb, bf16* __restrict__ thi,
                             bf16* __restrict__ tlo)
{
    long long idx = (long long)blockIdx.x * blockDim.x + threadIdx.x;
    if (idx >= (long long)BATCH * TSEQ * D_MODEL) return;
    int d = (int)(idx % D_MODEL);
    long long bi = idx / D_MODEL;
    int i = (int)(bi % TSEQ);
    int b = (int)(bi / TSEQ);
    const float* base = tt + (long long)b * TSEQ * D_MODEL + d;
    float acc = cb[d];
#pragma unroll
    for (int k = 0; k < KSIZE; k++) {
        int src = i - (KSIZE - 1) + k;
        if (src >= 0) acc += base[(long long)src * D_MODEL] * cw[d * KSIZE + k];
    }
    bf16 h, l; split_bf16(acc, h, l);
    thi[idx] = h; tlo[idx] = l;
}

__global__ void k_swiglu_split(const float* __restrict__ gu, bf16* __restrict__ hhi,
                               bf16* __restrict__ hlo)
{
    long long g = (long long)blockIdx.x * blockDim.x + threadIdx.x;
    if (g >= (long long)8192 * 1024) return;
    long long m = g >> 10;
    int c4 = (int)(g & 1023) * 4;
    const float* p = gu + m * 8192 + c4;
    float4 G = *(const float4*)p;
    float4 U = *(const float4*)(p + 4096);
    bf16 vh[4], vl[4];
    float gg[4] = {G.x, G.y, G.z, G.w};
    float uu[4] = {U.x, U.y, U.z, U.w};
#pragma unroll
    for (int i = 0; i < 4; i++) {
        float s = gg[i] / (1.0f + expf(-gg[i]));
        split_bf16(s * uu[i], vh[i], vl[i]);
    }
    *(uint2*)(hhi + m * 4096 + c4) = *(uint2*)vh;
    *(uint2*)(hlo + m * 4096 + c4) = *(uint2*)vl;
}

// 64x64 bf16 transpose within each 4096x4096 batch slab
__global__ void k_transpose_bf16(const bf16* __restrict__ in, bf16* __restrict__ out)
{
    __shared__ bf16 tile[64][72];
    const size_t bo = (size_t)blockIdx.z * 4096 * 4096;
    in += bo; out += bo;
    const int r0 = blockIdx.y * 64, c0 = blockIdx.x * 64;
    for (int u = threadIdx.x; u < 512; u += 256) {
        int r = u >> 3, s = (u & 7) * 8;
        uint4 v = *(const uint4*)(in + (size_t)(r0 + r) * 4096 + c0 + s);
        *(uint4*)&tile[r][s] = v;
    }
    __syncthreads();
    for (int u = threadIdx.x; u < 512; u += 256) {
        int c = u >> 3, s = (u & 7) * 8;
        bf16 v[8];
#pragma unroll
        for (int i = 0; i < 8; i++) v[i] = tile[s + i][c];
        *(uint4*)(out + (size_t)(c0 + c) * 4096 + r0 + s) = *(uint4*)v;
    }
}

// tp (b:3840x1024 fp32) -> tpT hi/lo (b:1024x3840 bf16)
__global__ void k_convtrans_tp(const float* __restrict__ in, bf16* __restrict__ ohi,
                               bf16* __restrict__ olo)
{
    __shared__ float tile[64][68];
    in  += (size_t)blockIdx.z * 3840 * 1024;
    ohi += (size_t)blockIdx.z * 1024 * 3840;
    olo += (size_t)blockIdx.z * 1024 * 3840;
    const int r0 = blockIdx.y * 64;   // t' dim
    const int c0 = blockIdx.x * 64;   // d dim
    for (int u = threadIdx.x; u < 1024; u += 256) {
        int r = u >> 4, s = (u & 15) * 4;
        float4 v = *(const float4*)(in + (size_t)(r0 + r) * 1024 + c0 + s);
        *(float4*)&tile[r][s] = v;
    }
    __syncthreads();
    for (int u = threadIdx.x; u < 512; u += 256) {
        int c = u >> 3, s = (u & 7) * 8;
        bf16 vh[8], vl[8];
#pragma unroll
        for (int i = 0; i < 8; i++) split_bf16(tile[s + i][c], vh[i], vl[i]);
        size_t o = (size_t)(c0 + c) * 3840 + r0 + s;
        *(uint4*)(ohi + o) = *(uint4*)vh;
        *(uint4*)(olo + o) = *(uint4*)vl;
    }
}

// cumsum of dd over chunks -> w_adapted hi/lo (bf16)
__global__ void k_wadp(const float* __restrict__ dd, const float* __restrict__ wdown,
                       bf16* __restrict__ whi, bf16* __restrict__ wlo)
{
    long long i = (long long)blockIdx.x * blockDim.x + threadIdx.x;
    const long long DF = 1LL << 22;   // 1024*4096
    if (i >= BATCH * DF) return;
    int b = (int)(i >> 22);
    long long off = i & (DF - 1);
    float acc = wdown[off];
#pragma unroll
    for (int j = 0; j < 16; j++) {
        bf16 h, l; split_bf16(acc, h, l);
        size_t o = ((size_t)(b * 16 + j) << 22) + off;
        whi[o] = h; wlo[o] = l;
        if (j < 15) acc += TTT_LR * dd[((size_t)(b * 15 + j) << 22) + off];
    }
}

// ================= launch =================
extern "C" void kernel_launch(void* const* d_in, const int* in_sizes, int n_in,
                              void* d_out, int out_size)
{
    const float* x     = (const float*)d_in[0];
    const float* tt    = (const float*)d_in[1];
    const float* wgu   = (const float*)d_in[2];
    const float* wdown = (const float*)d_in[3];
    const float* proj  = (const float*)d_in[4];
    const float* cw    = (const float*)d_in[5];
    const float* cb    = (const float*)d_in[6];
    float* out = (float*)d_out;

    float *gu, *tp, *dd;
    bf16 *h_hi, *h_lo, *hT_hi, *hT_lo, *x_hi, *x_lo, *wgu_hi, *wgu_lo;
    bf16 *proj_hi, *proj_lo, *t_hi, *t_lo, *tpT_hi, *tpT_lo, *wa_hi, *wa_lo;
    cudaGetSymbolAddress((void**)&gu, g_gu);
    cudaGetSymbolAddress((void**)&tp, g_tp);
    cudaGetSymbolAddress((void**)&dd, g_dd);
    cudaGetSymbolAddress((void**)&h_hi, g_h_hi);   cudaGetSymbolAddress((void**)&h_lo, g_h_lo);
    cudaGetSymbolAddress((void**)&hT_hi, g_hT_hi); cudaGetSymbolAddress((void**)&hT_lo, g_hT_lo);
    cudaGetSymbolAddress((void**)&x_hi, g_x_hi);   cudaGetSymbolAddress((void**)&x_lo, g_x_lo);
    cudaGetSymbolAddress((void**)&wgu_hi, g_wgu_hi); cudaGetSymbolAddress((void**)&wgu_lo, g_wgu_lo);
    cudaGetSymbolAddress((void**)&proj_hi, g_proj_hi); cudaGetSymbolAddress((void**)&proj_lo, g_proj_lo);
    cudaGetSymbolAddress((void**)&t_hi, g_t_hi);   cudaGetSymbolAddress((void**)&t_lo, g_t_lo);
    cudaGetSymbolAddress((void**)&tpT_hi, g_tpT_hi); cudaGetSymbolAddress((void**)&tpT_lo, g_tpT_lo);
    cudaGetSymbolAddress((void**)&wa_hi, g_wa_hi); cudaGetSymbolAddress((void**)&wa_lo, g_wa_lo);

    cudaFuncSetAttribute(k_mma, cudaFuncAttributeMaxDynamicSharedMemorySize, SMEM_BYTES);

    // input conversions (fp32 -> bf16 hi/lo)
    k_convert<<<(int)((8192LL * 1024 + 255) / 256), 256>>>(x, x_hi, x_lo, 8192LL * 1024);
    k_convert<<<(int)((8192LL * 1024 + 255) / 256), 256>>>(wgu, wgu_hi, wgu_lo, 8192LL * 1024);
    k_convert<<<(int)((1024LL * 1024 + 255) / 256), 256>>>(proj, proj_hi, proj_lo, 1024LL * 1024);
    // causal depthwise conv (+split)
    k_conv_split<<<(BATCH * TSEQ * D_MODEL + 255) / 256, 256>>>(tt, cw, cb, t_hi, t_lo);

    // G1: gu[8192,8192] = x @ wgu^T, K=1024
    k_mma<<<dim3(8192 / BN, 8192 / BM, 1), 256, SMEM_BYTES>>>(
        x_hi, x_lo, 1024, wgu_hi, wgu_lo, 1024, gu, 8192, 1024, 1,
        0, 0, 0, 0, 0, 0);

    // SwiGLU -> h hi/lo
    k_swiglu_split<<<(int)((8192LL * 1024 + 255) / 256), 256>>>(gu, h_hi, h_lo);
    // h transpose per batch -> hT hi/lo
    k_transpose_bf16<<<dim3(64, 64, BATCH), 256>>>(h_hi, hT_hi);
    k_transpose_bf16<<<dim3(64, 64, BATCH), 256>>>(h_lo, hT_lo);

    // G2: tp[b,3840,1024] = t @ proj^T, K=1024, z=batch
    k_mma<<<dim3(1024 / BN, 3840 / BM, BATCH), 256, SMEM_BYTES>>>(
        t_hi, t_lo, 1024, proj_hi, proj_lo, 1024, tp, 1024, 1024, 1,
        4096LL * 1024, 0, 0, 0, 3840LL * 1024, 0);

    // tp -> tpT hi/lo
    k_convtrans_tp<<<dim3(16, 60, BATCH), 256>>>(tp, tpT_hi, tpT_lo);

    // G3: dd[z=b*15+j][1024,4096] = tpT_chunk @ hT_chunk^T, K=256
    k_mma<<<dim3(4096 / BN, 1024 / BM, BATCH * 15), 256, SMEM_BYTES>>>(
        tpT_hi, tpT_lo, 3840, hT_hi, hT_lo, 4096, dd, 4096, 256, 15,
        3840LL * 1024, 256, 4096LL * 4096, 256, 15LL * 1024 * 4096, 1024LL * 4096);

    // cumsum -> w_adapted hi/lo
    k_wadp<<<(int)((BATCH * (1LL << 22) + 255) / 256), 256>>>(dd, wdown, wa_hi, wa_lo);

    // G4: out[b,j*256..][1024] = h_chunk @ wa[b,j]^T, K=4096, z=b*16+j
    k_mma<<<dim3(1024 / BN, CHUNK / BM, BATCH * 16), 256, SMEM_BYTES>>>(
        h_hi, h_lo, 4096, wa_hi, wa_lo, 4096, out, 1024, 4096, 16,
        4096LL * 4096, 256LL * 4096, 16LL * 1024 * 4096, 1024LL * 4096,
        4096LL * 1024, 256LL * 1024);
}

// round 4
// speedup vs baseline: 2.2542x; 1.1246x over previous
#include <cuda_runtime.h>
#include <cuda_bf16.h>
#include <cstdint>

#define TTT_LR  0.01f
#define KSIZE   5

#define BM 128
#define BN 128
#define BK 32
#define STAGES 3
#define APITCH 80
#define ASZ (128 * APITCH)
#define SMEM_NT (STAGES * 2 * ASZ)      // 61440
#define TPITCH 272
#define TSZ (32 * TPITCH)               // 8704
#define SMEM_TN (STAGES * 2 * TSZ)      // 52224

typedef unsigned long long u64;
typedef __nv_bfloat16 bf16;

// ================= device scratch =================
__device__ __align__(16) bf16  g_h_hi [(size_t)8192 * 4096];
__device__ __align__(16) bf16  g_h_lo [(size_t)8192 * 4096];
__device__ __align__(16) bf16  g_x_hi [(size_t)8192 * 1024];
__device__ __align__(16) bf16  g_x_lo [(size_t)8192 * 1024];
__device__ __align__(16) bf16  g_wgu_hi[(size_t)8192 * 1024];
__device__ __align__(16) bf16  g_wgu_lo[(size_t)8192 * 1024];
__device__ __align__(16) bf16  g_proj_hi[(size_t)1024 * 1024];
__device__ __align__(16) bf16  g_proj_lo[(size_t)1024 * 1024];
__device__ __align__(16) bf16  g_t_hi [(size_t)2 * 4096 * 1024];
__device__ __align__(16) bf16  g_t_lo [(size_t)2 * 4096 * 1024];
__device__ __align__(16) bf16  g_tp_hi[(size_t)2 * 3840 * 1024];
__device__ __align__(16) bf16  g_tp_lo[(size_t)2 * 3840 * 1024];
__device__ __align__(16) float g_dd   [(size_t)2 * 15 * 1024 * 4096];   // 503MB
__device__ __align__(16) bf16  g_wa_hi[(size_t)2 * 16 * 1024 * 4096];   // 268MB
__device__ __align__(16) bf16  g_wa_lo[(size_t)2 * 16 * 1024 * 4096];   // 268MB
__device__ __align__(16) float g_p4   [(size_t)4 * 2 * 4096 * 1024];    // 134MB

// ================= PTX helpers =================
__device__ __forceinline__ uint32_t smem_u32(const void* p) {
    uint32_t a;
    asm("{ .reg .u64 t; cvta.to.shared.u64 t, %1; cvt.u32.u64 %0, t; }" : "=r"(a) : "l"(p));
    return a;
}
__device__ __forceinline__ void cp_async16(uint32_t sdst, const void* gsrc) {
    asm volatile("cp.async.cg.shared.global [%0], [%1], 16;" :: "r"(sdst), "l"(gsrc) : "memory");
}
__device__ __forceinline__ void cp_commit() {
    asm volatile("cp.async.commit_group;" ::: "memory");
}
__device__ __forceinline__ void ldm_x4(uint32_t addr, uint32_t& r0, uint32_t& r1,
                                       uint32_t& r2, uint32_t& r3) {
    asm volatile("ldmatrix.sync.aligned.m8n8.x4.shared.b16 {%0,%1,%2,%3}, [%4];"
                 : "=r"(r0), "=r"(r1), "=r"(r2), "=r"(r3) : "r"(addr));
}
__device__ __forceinline__ void ldm_x4_t(uint32_t addr, uint32_t& r0, uint32_t& r1,
                                         uint32_t& r2, uint32_t& r3) {
    asm volatile("ldmatrix.sync.aligned.m8n8.x4.trans.shared.b16 {%0,%1,%2,%3}, [%4];"
                 : "=r"(r0), "=r"(r1), "=r"(r2), "=r"(r3) : "r"(addr));
}
__device__ __forceinline__ void mma16816(float* c, const uint32_t* a, uint32_t b0, uint32_t b1) {
    asm volatile("mma.sync.aligned.m16n8k16.row.col.f32.bf16.bf16.f32 "
                 "{%0,%1,%2,%3}, {%4,%5,%6,%7}, {%8,%9}, {%0,%1,%2,%3};"
                 : "+f"(c[0]), "+f"(c[1]), "+f"(c[2]), "+f"(c[3])
                 : "r"(a[0]), "r"(a[1]), "r"(a[2]), "r"(a[3]), "r"(b0), "r"(b1));
}
__device__ __forceinline__ void split_bf16(float v, bf16& hi, bf16& lo) {
    hi = __float2bfloat16(v);
    lo = __float2bfloat16(v - __bfloat162float(hi));
}
__device__ __forceinline__ uint32_t pack_bf(bf16 a, bf16 b) {
    return (uint32_t)__bfloat16_as_ushort(a) | ((uint32_t)__bfloat16_as_ushort(b) << 16);
}

// ================= NT GEMM (C = A @ B^T), bf16 hi/lo 3-term split =================
// SPLIT_OUT=0: fp32 C.  SPLIT_OUT=1: write bf16 hi/lo split to Chi/Clo.
template <int SPLIT_OUT>
__global__ __launch_bounds__(256, 2) void k_mma(
    const bf16* __restrict__ Ahi, const bf16* __restrict__ Alo, long long lda,
    const bf16* __restrict__ Bhi, const bf16* __restrict__ Blo, long long ldb,
    float* __restrict__ C, bf16* __restrict__ Chi, bf16* __restrict__ Clo,
    long long ldc, int K, int Z2,
    long long sA1, long long sA2, long long sB1, long long sB2,
    long long sC1, long long sC2)
{
    extern __shared__ char smem[];
    const uint32_t sb = smem_u32(smem);
    const int tid = threadIdx.x;
    const int lane = tid & 31;
    const int warp = tid >> 5;
    const int wm = warp >> 2;
    const int wn = warp & 3;

    const int z = blockIdx.z, z1 = z / Z2, z2 = z % Z2;
    const long long aoff = (long long)z1 * sA1 + (long long)z2 * sA2 + (long long)blockIdx.y * BM * lda;
    const long long boff = (long long)z1 * sB1 + (long long)z2 * sB2 + (long long)blockIdx.x * BN * ldb;
    Ahi += aoff; Alo += aoff;
    Bhi += boff; Blo += boff;
    const long long coff = (long long)z1 * sC1 + (long long)z2 * sC2
                         + (long long)blockIdx.y * BM * ldc + (long long)blockIdx.x * BN;

    const int KI = K / BK;
    const int total = 3 * KI;

    float acc[4][4][4];
#pragma unroll
    for (int i = 0; i < 4; i++)
#pragma unroll
        for (int n = 0; n < 4; n++)
#pragma unroll
            for (int r = 0; r < 4; r++) acc[i][n][r] = 0.f;

    const int lrow0 = tid >> 2;
    const int lko   = (tid & 3);

    auto issue_load = [&](int it) {
        const int seg = (it >= 2 * KI) ? 2 : (it >= KI ? 1 : 0);
        const bf16* Ag = (seg == 2) ? Alo : Ahi;
        const bf16* Bg = (seg == 1) ? Blo : Bhi;
        const int kk = (it - seg * KI) * BK;
        const int s = it % STAGES;
        const uint32_t sa = sb + s * ASZ;
        const uint32_t sB = sb + (STAGES + s) * ASZ;
#pragma unroll
        for (int q = 0; q < 2; q++) {
            const int row = lrow0 + q * 64;
            const uint32_t so = (uint32_t)row * APITCH + lko * 16;
            cp_async16(sa + so, Ag + (size_t)row * lda + kk + lko * 8);
            cp_async16(sB + so, Bg + (size_t)row * ldb + kk + lko * 8);
        }
    };

#pragma unroll
    for (int s = 0; s < STAGES - 1; s++) {
        if (s < total) issue_load(s);
        cp_commit();
    }

    const uint32_t aRow = (uint32_t)(wm * 64 + (lane & 15));
    const uint32_t bRow = (uint32_t)(wn * 32 + (lane & 15));
    const uint32_t kByte = (uint32_t)((lane >> 4) * 16);

    for (int it = 0; it < total; ++it) {
        asm volatile("cp.async.wait_group %0;" :: "n"(STAGES - 2) : "memory");
        __syncthreads();
        const int nx = it + STAGES - 1;
        if (nx < total) issue_load(nx);
        cp_commit();

        const int s = it % STAGES;
        const uint32_t sa = sb + s * ASZ;
        const uint32_t sB = sb + (STAGES + s) * ASZ;
#pragma unroll
        for (int k16 = 0; k16 < 2; k16++) {
            uint32_t a[4][4], b[2][4];
#pragma unroll
            for (int i = 0; i < 4; i++)
                ldm_x4(sa + (aRow + i * 16) * APITCH + kByte + k16 * 32,
                       a[i][0], a[i][1], a[i][2], a[i][3]);
#pragma unroll
            for (int j = 0; j < 2; j++)
                ldm_x4(sB + (bRow + j * 16) * APITCH + kByte + k16 * 32,
                       b[j][0], b[j][1], b[j][2], b[j][3]);
#pragma unroll
            for (int i = 0; i < 4; i++) {
#pragma unroll
                for (int n = 0; n < 4; n++) {
                    const int j = n >> 1, h = n & 1;
                    mma16816(acc[i][n], a[i], b[j][h], b[j][h + 2]);
                }
            }
        }
    }

    const int g = lane >> 2, t2 = (lane & 3) * 2;
#pragma unroll
    for (int i = 0; i < 4; i++) {
        const int r = wm * 64 + i * 16 + g;
#pragma unroll
        for (int n = 0; n < 4; n++) {
            const int cc = wn * 32 + (n >> 1) * 16 + (n & 1) * 8 + t2;
            if (SPLIT_OUT) {
                bf16 h0, l0, h1, l1;
                split_bf16(acc[i][n][0], h0, l0); split_bf16(acc[i][n][1], h1, l1);
                *(uint32_t*)(Chi + coff + (size_t)r * ldc + cc) = pack_bf(h0, h1);
                *(uint32_t*)(Clo + coff + (size_t)r * ldc + cc) = pack_bf(l0, l1);
                split_bf16(acc[i][n][2], h0, l0); split_bf16(acc[i][n][3], h1, l1);
                *(uint32_t*)(Chi + coff + (size_t)(r + 8) * ldc + cc) = pack_bf(h0, h1);
                *(uint32_t*)(Clo + coff + (size_t)(r + 8) * ldc + cc) = pack_bf(l0, l1);
            } else {
                *(float2*)&C[coff + (size_t)r * ldc + cc]       = make_float2(acc[i][n][0], acc[i][n][1]);
                *(float2*)&C[coff + (size_t)(r + 8) * ldc + cc] = make_float2(acc[i][n][2], acc[i][n][3]);
            }
        }
    }
}

// ================= TN GEMM (C[m,n] = sum_k A[k,m]*B[k,n]), trans-ldmatrix =================
__global__ __launch_bounds__(256, 2) void k_mma_tn(
    const bf16* __restrict__ Ahi, const bf16* __restrict__ Alo, long long lda,
    const bf16* __restrict__ Bhi, const bf16* __restrict__ Blo, long long ldb,
    float* __restrict__ C, long long ldc, int K, int Z2,
    long long sA1, long long sA2, long long sB1, long long sB2,
    long long sC1, long long sC2)
{
    extern __shared__ char smem[];
    const uint32_t sb = smem_u32(smem);
    const int tid = threadIdx.x;
    const int lane = tid & 31;
    const int warp = tid >> 5;
    const int wm = warp >> 2;
    const int wn = warp & 3;

    const int z = blockIdx.z, z1 = z / Z2, z2 = z % Z2;
    const long long aoff = (long long)z1 * sA1 + (long long)z2 * sA2 + (long long)blockIdx.y * BM;
    const long long boff = (long long)z1 * sB1 + (long long)z2 * sB2 + (long long)blockIdx.x * BN;
    Ahi += aoff; Alo += aoff;
    Bhi += boff; Blo += boff;
    C   += (long long)z1 * sC1 + (long long)z2 * sC2
         + (long long)blockIdx.y * BM * ldc + (long long)blockIdx.x * BN;

    const int KI = K / BK;
    const int total = 3 * KI;

    float acc[4][4][4];
#pragma unroll
    for (int i = 0; i < 4; i++)
#pragma unroll
        for (int n = 0; n < 4; n++)
#pragma unroll
            for (int r = 0; r < 4; r++) acc[i][n][r] = 0.f;

    auto issue_load = [&](int it) {
        const int seg = (it >= 2 * KI) ? 2 : (it >= KI ? 1 : 0);
        const bf16* Ag = (seg == 2) ? Alo : Ahi;
        const bf16* Bg = (seg == 1) ? Blo : Bhi;
        const int kk = (it - seg * KI) * BK;
        const int s = it % STAGES;
        const uint32_t sa = sb + s * TSZ;
        const uint32_t sB = sb + (STAGES + s) * TSZ;
#pragma unroll
        for (int q = 0; q < 2; q++) {
            const int c = tid + q * 256;
            const int row = c >> 4, col = c & 15;
            const uint32_t so = (uint32_t)row * TPITCH + col * 16;
            cp_async16(sa + so, Ag + (size_t)(kk + row) * lda + col * 8);
            cp_async16(sB + so, Bg + (size_t)(kk + row) * ldb + col * 8);
        }
    };

#pragma unroll
    for (int s = 0; s < STAGES - 1; s++) {
        if (s < total) issue_load(s);
        cp_commit();
    }

    // trans-ldmatrix lane addressing
    const uint32_t aK = (lane & 7) + ((lane >> 4) & 1) * 8;
    const uint32_t aM = (uint32_t)(wm * 64) * 2 + ((lane >> 3) & 1) * 16;
    const uint32_t bK = (lane & 7) + ((lane >> 3) & 1) * 8;
    const uint32_t bN = (uint32_t)(wn * 32) * 2 + ((lane >> 4) & 1) * 16;

    for (int it = 0; it < total; ++it) {
        asm volatile("cp.async.wait_group %0;" :: "n"(STAGES - 2) : "memory");
        __syncthreads();
        const int nx = it + STAGES - 1;
        if (nx < total) issue_load(nx);
        cp_commit();

        const int s = it % STAGES;
        const uint32_t sa = sb + s * TSZ;
        const uint32_t sB = sb + (STAGES + s) * TSZ;
#pragma unroll
        for (int k16 = 0; k16 < 2; k16++) {
            uint32_t a[4][4], b[2][4];
#pragma unroll
            for (int i = 0; i < 4; i++)
                ldm_x4_t(sa + (k16 * 16 + aK) * TPITCH + aM + i * 32,
                         a[i][0], a[i][1], a[i][2], a[i][3]);
#pragma unroll
            for (int gidx = 0; gidx < 2; gidx++)
                ldm_x4_t(sB + (k16 * 16 + bK) * TPITCH + bN + gidx * 32,
                         b[gidx][0], b[gidx][1], b[gidx][2], b[gidx][3]);
#pragma unroll
            for (int i = 0; i < 4; i++) {
#pragma unroll
                for (int n = 0; n < 4; n++) {
                    const int gr = n >> 1, h = (n & 1) * 2;
                    mma16816(acc[i][n], a[i], b[gr][h], b[gr][h + 1]);
                }
            }
        }
    }

    const int g = lane >> 2, t2 = (lane & 3) * 2;
#pragma unroll
    for (int i = 0; i < 4; i++) {
        const int r = wm * 64 + i * 16 + g;
#pragma unroll
        for (int n = 0; n < 4; n++) {
            const int cc = wn * 32 + (n >> 1) * 16 + (n & 1) * 8 + t2;
            *(float2*)&C[(size_t)r * ldc + cc]       = make_float2(acc[i][n][0], acc[i][n][1]);
            *(float2*)&C[(size_t)(r + 8) * ldc + cc] = make_float2(acc[i][n][2], acc[i][n][3]);
        }
    }
}

// ================= fused G1 + SwiGLU =================
// block: 128 rows of x, 64 cols f; computes gate & up tiles, writes h hi/lo.
__global__ __launch_bounds__(256, 2) void k_mma_swiglu(
    const bf16* __restrict__ Ahi, const bf16* __restrict__ Alo,
    const bf16* __restrict__ Bhi, const bf16* __restrict__ Blo,
    bf16* __restrict__ Hhi, bf16* __restrict__ Hlo)
{
    extern __shared__ char smem[];
    const uint32_t sb = smem_u32(smem);
    const int tid = threadIdx.x;
    const int lane = tid & 31;
    const int warp = tid >> 5;
    const int wm = warp >> 2;
    const int wn = warp & 3;

    // supertile swizzle for L2 reuse (gridDim = 64 x 64)
    int l = blockIdx.y * gridDim.x + blockIdx.x;
    const int per = 8 * gridDim.x;
    const int grp = l / per, rem = l % per;
    const int by = grp * 8 + (rem & 7);
    const int bx = rem >> 3;

    const int KI = 32;          // 1024/32
    const int total = 96;

    float accg[4][2][4], accu[4][2][4];
#pragma unroll
    for (int i = 0; i < 4; i++)
#pragma unroll
        for (int n = 0; n < 2; n++)
#pragma unroll
            for (int r = 0; r < 4; r++) { accg[i][n][r] = 0.f; accu[i][n][r] = 0.f; }

    const int lrow0 = tid >> 2;
    const int lko   = (tid & 3);

    auto issue_load = [&](int it) {
        const int seg = (it >= 2 * KI) ? 2 : (it >= KI ? 1 : 0);
        const bf16* Ag = (seg == 2) ? Alo : Ahi;
        const bf16* Bg = (seg == 1) ? Blo : Bhi;
        const int kk = (it - seg * KI) * BK;
        const int s = it % STAGES;
        const uint32_t sa = sb + s * ASZ;
        const uint32_t sB = sb + (STAGES + s) * ASZ;
#pragma unroll
        for (int q = 0; q < 2; q++) {
            const int row = lrow0 + q * 64;
            const uint32_t so = (uint32_t)row * APITCH + lko * 16;
            cp_async16(sa + so, Ag + (size_t)(by * 128 + row) * 1024 + kk + lko * 8);
            const size_t grow = (q == 0) ? (size_t)(bx * 64 + lrow0)
                                         : (size_t)(4096 + bx * 64 + lrow0);
            cp_async16(sB + so, Bg + grow * 1024 + kk + lko * 8);
        }
    };

#pragma unroll
    for (int s = 0; s < STAGES - 1; s++) { issue_load(s); cp_commit(); }

    const uint32_t aRow = (uint32_t)(wm * 64 + (lane & 15));
    const uint32_t gRow = (uint32_t)(wn * 16 + (lane & 15));
    const uint32_t uRow = gRow + 64;
    const uint32_t kByte = (uint32_t)((lane >> 4) * 16);

    for (int it = 0; it < total; ++it) {
        asm volatile("cp.async.wait_group %0;" :: "n"(STAGES - 2) : "memory");
        __syncthreads();
        const int nx = it + STAGES - 1;
        if (nx < total) issue_load(nx);
        cp_commit();

        const int s = it % STAGES;
        const uint32_t sa = sb + s * ASZ;
        const uint32_t sB = sb + (STAGES + s) * ASZ;
#pragma unroll
        for (int k16 = 0; k16 < 2; k16++) {
            uint32_t a[4][4], bg[4], bu[4];
#pragma unroll
            for (int i = 0; i < 4; i++)
                ldm_x4(sa + (aRow + i * 16) * APITCH + kByte + k16 * 32,
                       a[i][0], a[i][1], a[i][2], a[i][3]);
            ldm_x4(sB + gRow * APITCH + kByte + k16 * 32, bg[0], bg[1], bg[2], bg[3]);
            ldm_x4(sB + uRow * APITCH + kByte + k16 * 32, bu[0], bu[1], bu[2], bu[3]);
#pragma unroll
            for (int i = 0; i < 4; i++) {
#pragma unroll
                for (int n = 0; n < 2; n++) {
                    mma16816(accg[i][n], a[i], bg[n], bg[n + 2]);
                    mma16816(accu[i][n], a[i], bu[n], bu[n + 2]);
                }
            }
        }
    }

    const int g = lane >> 2, t2 = (lane & 3) * 2;
#pragma unroll
    for (int i = 0; i < 4; i++) {
#pragma unroll
        for (int n = 0; n < 2; n++) {
            const int col = bx * 64 + wn * 16 + n * 8 + t2;
#pragma unroll
            for (int half = 0; half < 2; half++) {
                const size_t row = (size_t)by * 128 + wm * 64 + i * 16 + g + half * 8;
                float g0 = accg[i][n][half * 2 + 0], g1 = accg[i][n][half * 2 + 1];
                float u0 = accu[i][n][half * 2 + 0], u1 = accu[i][n][half * 2 + 1];
                float h0 = g0 / (1.0f + expf(-g0)) * u0;
                float h1 = g1 / (1.0f + expf(-g1)) * u1;
                bf16 h0h, h0l, h1h, h1l;
                split_bf16(h0, h0h, h0l); split_bf16(h1, h1h, h1l);
                *(uint32_t*)(Hhi + row * 4096 + col) = pack_bf(h0h, h1h);
                *(uint32_t*)(Hlo + row * 4096 + col) = pack_bf(h0l, h1l);
            }
        }
    }
}

// ================= elementwise kernels =================
__global__ void k_convert(const float* __restrict__ in, bf16* __restrict__ hi,
                          bf16* __restrict__ lo, long long n)
{
    long long i = (long long)blockIdx.x * blockDim.x + threadIdx.x;
    if (i >= n) return;
    bf16 h, l; split_bf16(in[i], h, l);
    hi[i] = h; lo[i] = l;
}

__global__ void k_conv_split(const float* __restrict__ tt, const float* __restrict__ cw,
                             const float* __restrict__ cb, bf16* __restrict__ thi,
                             bf16* __restrict__ tlo)
{
    long long idx = (long long)blockIdx.x * blockDim.x + threadIdx.x;
    if (idx >= (long long)2 * 4096 * 1024) return;
    int d = (int)(idx & 1023);
    long long bi = idx >> 10;
    int i = (int)(bi & 4095);
    int b = (int)(bi >> 12);
    const float* base = tt + (long long)b * 4096 * 1024 + d;
    float acc = cb[d];
#pragma unroll
    for (int k = 0; k < KSIZE; k++) {
        int src = i - (KSIZE - 1) + k;
        if (src >= 0) acc += base[(long long)src * 1024 ] * cw[d * KSIZE + k];
    }
    bf16 h, l; split_bf16(acc, h, l);
    thi[idx] = h; tlo[idx] = l;
}

// cumsum of dd over chunks -> w_adapted hi/lo (bf16)
__global__ void k_wadp(const float* __restrict__ dd, const float* __restrict__ wdown,
                       bf16* __restrict__ whi, bf16* __restrict__ wlo)
{
    long long i = (long long)blockIdx.x * blockDim.x + threadIdx.x;
    const long long DF = 1LL << 22;
    if (i >= 2 * DF) return;
    int b = (int)(i >> 22);
    long long off = i & (DF - 1);
    float acc = wdown[off];
#pragma unroll
    for (int j = 0; j < 16; j++) {
        bf16 h, l; split_bf16(acc, h, l);
        size_t o = ((size_t)(b * 16 + j) << 22) + off;
        whi[o] = h; wlo[o] = l;
        if (j < 15) acc += TTT_LR * dd[((size_t)(b * 15 + j) << 22) + off];
    }
}

// reduce 4 split-K partials -> out
__global__ void k_reduce4(const float* __restrict__ p, float* __restrict__ out)
{
    const long long N = 2LL * 4096 * 1024;
    long long i = ((long long)blockIdx.x * blockDim.x + threadIdx.x) * 4;
    if (i >= N) return;
    float4 a = *(const float4*)(p + i);
    float4 b = *(const float4*)(p + N + i);
    float4 c = *(const float4*)(p + 2 * N + i);
    float4 d = *(const float4*)(p + 3 * N + i);
    *(float4*)(out + i) = make_float4(a.x + b.x + c.x + d.x, a.y + b.y + c.y + d.y,
                                      a.z + b.z + c.z + d.z, a.w + b.w + c.w + d.w);
}

// ================= launch =================
extern "C" void kernel_launch(void* const* d_in, const int* in_sizes, int n_in,
                              void* d_out, int out_size)
{
    const float* x     = (const float*)d_in[0];
    const float* tt    = (const float*)d_in[1];
    const float* wgu   = (const float*)d_in[2];
    const float* wdown = (const float*)d_in[3];
    const float* proj  = (const float*)d_in[4];
    const float* cw    = (const float*)d_in[5];
    const float* cb    = (const float*)d_in[6];
    float* out = (float*)d_out;

    bf16 *h_hi, *h_lo, *x_hi, *x_lo, *wgu_hi, *wgu_lo, *proj_hi, *proj_lo;
    bf16 *t_hi, *t_lo, *tp_hi, *tp_lo, *wa_hi, *wa_lo;
    float *dd, *p4;
    cudaGetSymbolAddress((void**)&h_hi, g_h_hi);     cudaGetSymbolAddress((void**)&h_lo, g_h_lo);
    cudaGetSymbolAddress((void**)&x_hi, g_x_hi);     cudaGetSymbolAddress((void**)&x_lo, g_x_lo);
    cudaGetSymbolAddress((void**)&wgu_hi, g_wgu_hi); cudaGetSymbolAddress((void**)&wgu_lo, g_wgu_lo);
    cudaGetSymbolAddress((void**)&proj_hi, g_proj_hi); cudaGetSymbolAddress((void**)&proj_lo, g_proj_lo);
    cudaGetSymbolAddress((void**)&t_hi, g_t_hi);     cudaGetSymbolAddress((void**)&t_lo, g_t_lo);
    cudaGetSymbolAddress((void**)&tp_hi, g_tp_hi);   cudaGetSymbolAddress((void**)&tp_lo, g_tp_lo);
    cudaGetSymbolAddress((void**)&wa_hi, g_wa_hi);   cudaGetSymbolAddress((void**)&wa_lo, g_wa_lo);
    cudaGetSymbolAddress((void**)&dd, g_dd);
    cudaGetSymbolAddress((void**)&p4, g_p4);

    cudaFuncSetAttribute(k_mma<0>, cudaFuncAttributeMaxDynamicSharedMemorySize, SMEM_NT);
    cudaFuncSetAttribute(k_mma<1>, cudaFuncAttributeMaxDynamicSharedMemorySize, SMEM_NT);
    cudaFuncSetAttribute(k_mma_tn, cudaFuncAttributeMaxDynamicSharedMemorySize, SMEM_TN);
    cudaFuncSetAttribute(k_mma_swiglu, cudaFuncAttributeMaxDynamicSharedMemorySize, SMEM_NT);

    // conversions
    k_convert<<<(int)((8192LL * 1024 + 255) / 256), 256>>>(x, x_hi, x_lo, 8192LL * 1024);
    k_convert<<<(int)((8192LL * 1024 + 255) / 256), 256>>>(wgu, wgu_hi, wgu_lo, 8192LL * 1024);
    k_convert<<<(int)((1024LL * 1024 + 255) / 256), 256>>>(proj, proj_hi, proj_lo, 1024LL * 1024);
    k_conv_split<<<(2 * 4096 * 1024 + 255) / 256, 256>>>(tt, cw, cb, t_hi, t_lo);

    // G1 fused with SwiGLU -> h hi/lo
    k_mma_swiglu<<<dim3(64, 64, 1), 256, SMEM_NT>>>(x_hi, x_lo, wgu_hi, wgu_lo, h_hi, h_lo);

    // G2: tp[b, 3840, 1024] = t @ proj^T (split bf16 out)
    k_mma<1><<<dim3(8, 30, 2), 256, SMEM_NT>>>(
        t_hi, t_lo, 1024, proj_hi, proj_lo, 1024,
        nullptr, tp_hi, tp_lo, 1024, 1024, 1,
        4096LL * 1024, 0, 0, 0, 3840LL * 1024, 0);

    // G3 (TN): dd[z][1024,4096] = sum_c tp[c,d] * h[c,f], K=256, z = b*15+j
    k_mma_tn<<<dim3(32, 8, 30), 256, SMEM_TN>>>(
        tp_hi, tp_lo, 1024, h_hi, h_lo, 4096, dd, 4096, 256, 15,
        3840LL * 1024, 256LL * 1024, 4096LL * 4096, 256LL * 4096,
        15LL * 1024 * 4096, 1024LL * 4096);

    // cumsum -> w_adapted hi/lo
    k_wadp<<<(int)((2 * (1LL << 22) + 255) / 256), 256>>>(dd, wdown, wa_hi, wa_lo);

    // G4 split-K=4: partial[s] = h_chunk @ wa^T over K slice, z = (b*16+j)*4 + s
    k_mma<0><<<dim3(8, 2, 128), 256, SMEM_NT>>>(
        h_hi, h_lo, 4096, wa_hi, wa_lo, 4096,
        p4, nullptr, nullptr, 1024, 1024, 4,
        256LL * 4096, 1024, 1024LL * 4096, 1024,
        256LL * 1024, 2LL * 4096 * 1024);

    // reduce partials -> out
    k_reduce4<<<(int)((2LL * 4096 * 1024 / 4 + 255) / 256), 256>>>(p4, out);
}